// round 1
// baseline (speedup 1.0000x reference)
#include <cuda_runtime.h>
#include <cuda_bf16.h>
#include <stdint.h>

using bf16  = __nv_bfloat16;
using bf162 = __nv_bfloat162;

// ---------------- problem constants ----------------
constexpr int BATCH = 256;
constexpr int TOK   = 25;          // 1 query + 12 actives + 12 inactives
constexpr int M1    = BATCH * TOK; // 6400 rows
constexpr int DIM   = 1024;
constexpr int HA    = 4096;        // H*A
constexpr int NR    = 2048;
constexpr int NH    = 8;
constexpr int HD    = 512;
constexpr float BETA_F = 0.044194173824159216f;

// ---------------- device scratch (static, allocation-free) ----------------
__device__ bf16 g_Sf [(size_t)M1 * DIM];
__device__ bf16 g_ref[(size_t)NR * DIM];
__device__ bf16 g_Wq [(size_t)DIM * HA];
__device__ bf16 g_Wk [(size_t)DIM * HA];
__device__ bf16 g_Wv [(size_t)DIM * HA];
__device__ bf16 g_Wo [(size_t)HA * DIM];
__device__ bf16 g_Q  [(size_t)M1 * HA];
__device__ bf16 g_K  [(size_t)NR * HA];
__device__ bf16 g_Kt [(size_t)HA * NR];
__device__ bf16 g_V  [(size_t)NR * HA];
__device__ bf16 g_P  [(size_t)NH * M1 * NR];   // scores then probs (in place)
__device__ bf16 g_O  [(size_t)M1 * HA];
__device__ bf16 g_Sh [(size_t)M1 * DIM];

// ---------------- small PTX helpers ----------------
__device__ __forceinline__ uint32_t s2u(const void* p) {
    return (uint32_t)__cvta_generic_to_shared(p);
}
__device__ __forceinline__ void cp16(uint32_t d, const void* s) {
    asm volatile("cp.async.cg.shared.global [%0], [%1], 16;\n" :: "r"(d), "l"(s));
}
__device__ __forceinline__ void cp_commit() { asm volatile("cp.async.commit_group;\n" ::); }
__device__ __forceinline__ void cp_wait0()  { asm volatile("cp.async.wait_group 0;\n" ::); }

__device__ __forceinline__ void ldsm4(uint32_t& r0, uint32_t& r1, uint32_t& r2, uint32_t& r3, uint32_t a) {
    asm volatile("ldmatrix.sync.aligned.m8n8.x4.shared.b16 {%0,%1,%2,%3}, [%4];\n"
                 : "=r"(r0), "=r"(r1), "=r"(r2), "=r"(r3) : "r"(a));
}
__device__ __forceinline__ void ldsm4t(uint32_t& r0, uint32_t& r1, uint32_t& r2, uint32_t& r3, uint32_t a) {
    asm volatile("ldmatrix.sync.aligned.m8n8.x4.trans.shared.b16 {%0,%1,%2,%3}, [%4];\n"
                 : "=r"(r0), "=r"(r1), "=r"(r2), "=r"(r3) : "r"(a));
}
__device__ __forceinline__ void mma16816(float c[4],
                                         uint32_t a0, uint32_t a1, uint32_t a2, uint32_t a3,
                                         uint32_t b0, uint32_t b1) {
    asm volatile(
        "mma.sync.aligned.m16n8k16.row.col.f32.bf16.bf16.f32 "
        "{%0,%1,%2,%3}, {%4,%5,%6,%7}, {%8,%9}, {%0,%1,%2,%3};\n"
        : "+f"(c[0]), "+f"(c[1]), "+f"(c[2]), "+f"(c[3])
        : "r"(a0), "r"(a1), "r"(a2), "r"(a3), "r"(b0), "r"(b1));
}

// ---------------- packing kernels ----------------
__global__ void build_sf_kernel(const float* __restrict__ q,
                                const float* __restrict__ sa,
                                const float* __restrict__ si) {
    size_t i = (size_t)blockIdx.x * blockDim.x + threadIdx.x;  // one float4 per thread
    size_t e = i * 4;
    int row = (int)(e >> 10);
    int d   = (int)(e & 1023);
    int b = row / 25, t = row - b * 25;
    const float* src; size_t off;
    if (t == 0)        { src = q;  off = (size_t)b * 1024; }
    else if (t <= 12)  { src = sa; off = ((size_t)b * 12 + (t - 1)) * 1024; }
    else               { src = si; off = ((size_t)b * 12 + (t - 13)) * 1024; }
    float4 f = *(const float4*)(src + off + d);
    bf162 lo, hi;
    lo.x = __float2bfloat16(f.x); lo.y = __float2bfloat16(f.y);
    hi.x = __float2bfloat16(f.z); hi.y = __float2bfloat16(f.w);
    bf162* dst = (bf162*)(g_Sf + e);
    dst[0] = lo; dst[1] = hi;
}

__global__ void cvt_kernel(bf16* __restrict__ dst, const float* __restrict__ src) {
    size_t i = (size_t)blockIdx.x * blockDim.x + threadIdx.x;  // one float4 per thread
    float4 f = ((const float4*)src)[i];
    bf162 lo, hi;
    lo.x = __float2bfloat16(f.x); lo.y = __float2bfloat16(f.y);
    hi.x = __float2bfloat16(f.z); hi.y = __float2bfloat16(f.w);
    bf162* d = (bf162*)(dst + i * 4);
    d[0] = lo; d[1] = hi;
}

// K [NR][HA] -> Kt [HA][NR]
__global__ void transpose_kernel(const bf16* __restrict__ in, bf16* __restrict__ out) {
    __shared__ bf16 tile[32][33];
    int x0 = blockIdx.x * 32, y0 = blockIdx.y * 32;
    int tx = threadIdx.x, ty = threadIdx.y;
    for (int i = ty; i < 32; i += 8)
        tile[i][tx] = in[(size_t)(y0 + i) * HA + x0 + tx];
    __syncthreads();
    for (int i = ty; i < 32; i += 8)
        out[(size_t)(x0 + i) * NR + y0 + tx] = tile[tx][i];
}

// ---------------- generic bf16 GEMM: C = scale*(A@B) + bias ----------------
// 128x128 CTA tile, BK=32, 256 threads, cp.async double buffer, ldmatrix+mma.
// All dims are multiples of the tile sizes (asserted by construction).
__global__ __launch_bounds__(256, 1)
void gemm_kernel(const bf16* __restrict__ A, int lda, long long aZ,
                 const bf16* __restrict__ B, int ldb, long long bZ,
                 bf16* __restrict__ C, int ldc, long long cZ,
                 int K, const float* __restrict__ bias, float scale) {
    __shared__ bf16 As[2][128][40];   // +8 pad -> 80B row stride, conflict-free ldmatrix
    __shared__ bf16 Bs[2][32][136];   // +8 pad -> 272B row stride

    int z = blockIdx.z;
    A += (size_t)z * aZ;  B += (size_t)z * bZ;  C += (size_t)z * cZ;

    const int row0 = blockIdx.y * 128, col0 = blockIdx.x * 128;
    const int tid = threadIdx.x, lane = tid & 31, w = tid >> 5;
    const int wm = w >> 2, wn = w & 3;              // 2 x 4 warp grid, 64x32 per warp

    const int ar = tid >> 1, ac = (tid & 1) * 16;   // A tile gmem->smem mapping
    const int br = tid >> 3, bc = (tid & 7) * 16;   // B tile

    const bf16* Ag = A + (size_t)(row0 + ar) * lda + ac;
    const bf16* Bg = B + (size_t)br * ldb + col0 + bc;

    uint32_t sA[2], sB[2];
    sA[0] = s2u(&As[0][ar][ac]); sA[1] = s2u(&As[1][ar][ac]);
    sB[0] = s2u(&Bs[0][br][bc]); sB[1] = s2u(&Bs[1][br][bc]);

    float acc[4][4][4];
    #pragma unroll
    for (int i = 0; i < 4; i++)
        #pragma unroll
        for (int j = 0; j < 4; j++)
            #pragma unroll
            for (int k = 0; k < 4; k++) acc[i][j][k] = 0.f;

    auto issue = [&](int kt, int buf) {
        const bf16* a = Ag + kt * 32;
        cp16(sA[buf],      a);
        cp16(sA[buf] + 16, a + 8);
        const bf16* b = Bg + ((size_t)kt * 32) * ldb;
        cp16(sB[buf],      b);
        cp16(sB[buf] + 16, b + 8);
        cp_commit();
    };

    const int tiles = K >> 5;
    issue(0, 0);

    for (int kt = 0; kt < tiles; ++kt) {
        int buf = kt & 1;
        cp_wait0();
        __syncthreads();
        if (kt + 1 < tiles) issue(kt + 1, buf ^ 1);

        #pragma unroll
        for (int ks = 0; ks < 2; ++ks) {
            uint32_t a[4][4];
            #pragma unroll
            for (int mi = 0; mi < 4; ++mi) {
                uint32_t ad = s2u(&As[buf][wm * 64 + mi * 16 + (lane & 15)]
                                          [ks * 16 + ((lane >> 4) << 3)]);
                ldsm4(a[mi][0], a[mi][1], a[mi][2], a[mi][3], ad);
            }
            uint32_t bq[2][4];
            #pragma unroll
            for (int bj = 0; bj < 2; ++bj) {
                int r = ks * 16 + (lane & 7) + (((lane >> 3) & 1) << 3);
                int c = wn * 32 + bj * 16 + ((lane >> 4) << 3);
                uint32_t bd = s2u(&Bs[buf][r][c]);
                ldsm4t(bq[bj][0], bq[bj][1], bq[bj][2], bq[bj][3], bd);
            }
            #pragma unroll
            for (int mi = 0; mi < 4; ++mi)
                #pragma unroll
                for (int ni = 0; ni < 4; ++ni)
                    mma16816(acc[mi][ni],
                             a[mi][0], a[mi][1], a[mi][2], a[mi][3],
                             bq[ni >> 1][(ni & 1) * 2], bq[ni >> 1][(ni & 1) * 2 + 1]);
        }
        __syncthreads();
    }

    // epilogue
    #pragma unroll
    for (int mi = 0; mi < 4; ++mi) {
        #pragma unroll
        for (int ni = 0; ni < 4; ++ni) {
            int r = row0 + wm * 64 + mi * 16 + (lane >> 2);
            int c = col0 + wn * 32 + ni * 8 + (lane & 3) * 2;
            float b0 = 0.f, b1 = 0.f;
            if (bias) { b0 = bias[c]; b1 = bias[c + 1]; }
            bf162 lo, hi;
            lo.x = __float2bfloat16(acc[mi][ni][0] * scale + b0);
            lo.y = __float2bfloat16(acc[mi][ni][1] * scale + b1);
            hi.x = __float2bfloat16(acc[mi][ni][2] * scale + b0);
            hi.y = __float2bfloat16(acc[mi][ni][3] * scale + b1);
            *(bf162*)(C + (size_t)r * ldc + c)       = lo;
            *(bf162*)(C + (size_t)(r + 8) * ldc + c) = hi;
        }
    }
}

// ---------------- softmax over rows of 2048, in place ----------------
__global__ __launch_bounds__(256)
void softmax_kernel(bf16* __restrict__ P) {
    size_t row = blockIdx.x;
    bf162* p = (bf162*)(P + row * (size_t)NR);
    int t = threadIdx.x, lane = t & 31, w = t >> 5;
    __shared__ float red[8];

    float v[8];
    float mx = -1e30f;
    #pragma unroll
    for (int i = 0; i < 4; i++) {
        bf162 h = p[t + i * 256];
        v[2 * i]     = __bfloat162float(h.x);
        v[2 * i + 1] = __bfloat162float(h.y);
        mx = fmaxf(mx, fmaxf(v[2 * i], v[2 * i + 1]));
    }
    #pragma unroll
    for (int o = 16; o; o >>= 1) mx = fmaxf(mx, __shfl_xor_sync(0xffffffffu, mx, o));
    if (lane == 0) red[w] = mx;
    __syncthreads();
    mx = red[0];
    #pragma unroll
    for (int i = 1; i < 8; i++) mx = fmaxf(mx, red[i]);

    float s = 0.f;
    #pragma unroll
    for (int i = 0; i < 8; i++) { v[i] = __expf(v[i] - mx); s += v[i]; }
    #pragma unroll
    for (int o = 16; o; o >>= 1) s += __shfl_xor_sync(0xffffffffu, s, o);
    __syncthreads();
    if (lane == 0) red[w] = s;
    __syncthreads();
    s = red[0];
    #pragma unroll
    for (int i = 1; i < 8; i++) s += red[i];
    float inv = 1.0f / s;

    #pragma unroll
    for (int i = 0; i < 4; i++) {
        bf162 h;
        h.x = __float2bfloat16(v[2 * i] * inv);
        h.y = __float2bfloat16(v[2 * i + 1] * inv);
        p[t + i * 256] = h;
    }
}

// ---------------- residual + scatter into output sections ----------------
__global__ void scatter_kernel(const float* __restrict__ q,
                               const float* __restrict__ sa,
                               const float* __restrict__ si,
                               float* __restrict__ out) {
    size_t i = (size_t)blockIdx.x * blockDim.x + threadIdx.x;  // float2 granularity
    if (i >= (size_t)M1 * DIM / 2) return;
    int row = (int)(i >> 9);
    int d   = (int)((i & 511) * 2);
    int b = row / 25, t = row - b * 25;
    const float* src; size_t off, base;
    if (t == 0)       { src = q;  off = (size_t)b * 1024;                       base = 0; }
    else if (t <= 12) { src = sa; off = ((size_t)b * 12 + (t - 1)) * 1024;      base = (size_t)BATCH * 1024; }
    else              { src = si; off = ((size_t)b * 12 + (t - 13)) * 1024;     base = (size_t)BATCH * 1024 * 13; }
    float2 sv = *(const float2*)(src + off + d);
    bf162  h  = *(const bf162*)(g_Sh + (size_t)row * DIM + d);
    float2 o;
    o.x = sv.x + __bfloat162float(h.x);
    o.y = sv.y + __bfloat162float(h.y);
    *(float2*)(out + base + off + d) = o;
}

// ---------------- launch ----------------
extern "C" void kernel_launch(void* const* d_in, const int* in_sizes, int n_in,
                              void* d_out, int out_size) {
    const float* q   = (const float*)d_in[0];
    const float* sa  = (const float*)d_in[1];
    const float* si  = (const float*)d_in[2];
    // d_in[3], d_in[4]: support-set sizes (constant full), unused
    const float* ref = (const float*)d_in[5];
    const float* Wq  = (const float*)d_in[6];
    const float* bq  = (const float*)d_in[7];
    const float* Wk  = (const float*)d_in[8];
    const float* bk  = (const float*)d_in[9];
    const float* Wv  = (const float*)d_in[10];
    const float* bv  = (const float*)d_in[11];
    const float* Wo  = (const float*)d_in[12];
    const float* bo  = (const float*)d_in[13];
    float* out = (float*)d_out;

    bf16 *pSf, *pRef, *pWq, *pWk, *pWv, *pWo, *pQ, *pK, *pKt, *pV, *pP, *pO, *pSh;
    cudaGetSymbolAddress((void**)&pSf,  g_Sf);
    cudaGetSymbolAddress((void**)&pRef, g_ref);
    cudaGetSymbolAddress((void**)&pWq,  g_Wq);
    cudaGetSymbolAddress((void**)&pWk,  g_Wk);
    cudaGetSymbolAddress((void**)&pWv,  g_Wv);
    cudaGetSymbolAddress((void**)&pWo,  g_Wo);
    cudaGetSymbolAddress((void**)&pQ,   g_Q);
    cudaGetSymbolAddress((void**)&pK,   g_K);
    cudaGetSymbolAddress((void**)&pKt,  g_Kt);
    cudaGetSymbolAddress((void**)&pV,   g_V);
    cudaGetSymbolAddress((void**)&pP,   g_P);
    cudaGetSymbolAddress((void**)&pO,   g_O);
    cudaGetSymbolAddress((void**)&pSh,  g_Sh);

    // 1) pack inputs to bf16
    build_sf_kernel<<<(M1 * DIM / 4) / 256, 256>>>(q, sa, si);
    cvt_kernel<<<((size_t)NR  * DIM / 4) / 256, 256>>>(pRef, ref);
    cvt_kernel<<<((size_t)DIM * HA  / 4) / 256, 256>>>(pWq, Wq);
    cvt_kernel<<<((size_t)DIM * HA  / 4) / 256, 256>>>(pWk, Wk);
    cvt_kernel<<<((size_t)DIM * HA  / 4) / 256, 256>>>(pWv, Wv);
    cvt_kernel<<<((size_t)HA  * DIM / 4) / 256, 256>>>(pWo, Wo);

    // 2) projections
    gemm_kernel<<<dim3(HA / 128, M1 / 128, 1), 256>>>(pSf, DIM, 0, pWq, HA, 0, pQ, HA, 0, DIM, bq, 1.0f);
    gemm_kernel<<<dim3(HA / 128, NR / 128, 1), 256>>>(pRef, DIM, 0, pWk, HA, 0, pK, HA, 0, DIM, bk, 1.0f);
    gemm_kernel<<<dim3(HA / 128, NR / 128, 1), 256>>>(pRef, DIM, 0, pWv, HA, 0, pV, HA, 0, DIM, bv, 1.0f);

    // 3) K -> Kt so scores GEMM is NN
    transpose_kernel<<<dim3(HA / 32, NR / 32), dim3(32, 8)>>>(pK, pKt);

    // 4) scores[h] = BETA * Q_h @ Kt_h   (batched over heads via z)
    gemm_kernel<<<dim3(NR / 128, M1 / 128, NH), 256>>>(
        pQ, HA, HD,
        pKt, NR, (long long)HD * NR,
        pP, NR, (long long)M1 * NR,
        HD, nullptr, BETA_F);

    // 5) softmax rows
    softmax_kernel<<<NH * M1, 256>>>(pP);

    // 6) out[h] = P_h @ V_h
    gemm_kernel<<<dim3(HD / 128, M1 / 128, NH), 256>>>(
        pP, NR, (long long)M1 * NR,
        pV, HA, HD,
        pO, HA, HD,
        NR, nullptr, 1.0f);

    // 7) Sh = O @ Wo + bo
    gemm_kernel<<<dim3(DIM / 128, M1 / 128, 1), 256>>>(pO, HA, 0, pWo, DIM, 0, pSh, DIM, 0, HA, bo, 1.0f);

    // 8) residual + scatter into (query, actives, inactives) sections
    scatter_kernel<<<(M1 * DIM / 2 + 255) / 256, 256>>>(q, sa, si, out);
}

// round 4
// speedup vs baseline: 1.4099x; 1.4099x over previous
#include <cuda_runtime.h>
#include <cuda_bf16.h>
#include <stdint.h>

using bf16  = __nv_bfloat16;
using bf162 = __nv_bfloat162;

// ---------------- problem constants ----------------
constexpr int BATCH = 256;
constexpr int M1    = 6400;        // 256 * 25 rows
constexpr int DIM   = 1024;
constexpr int HA    = 4096;        // H*A
constexpr int NR    = 2048;
constexpr int NH    = 8;
constexpr int HD    = 512;
constexpr float BETA_F = 0.044194173824159216f;

// ---------------- device scratch (static, allocation-free) ----------------
__device__ __align__(128) bf16 g_Sf [(size_t)M1 * DIM];
__device__ __align__(128) bf16 g_ref[(size_t)NR * DIM];
__device__ __align__(128) bf16 g_Wq [(size_t)DIM * HA];
__device__ __align__(128) bf16 g_Wk [(size_t)DIM * HA];
__device__ __align__(128) bf16 g_Wv [(size_t)DIM * HA];
__device__ __align__(128) bf16 g_Wo [(size_t)HA * DIM];
__device__ __align__(128) bf16 g_Q  [(size_t)M1 * HA];
__device__ __align__(128) bf16 g_K  [(size_t)NR * HA];
__device__ __align__(128) bf16 g_Kt [(size_t)HA * NR];
__device__ __align__(128) bf16 g_V  [(size_t)NR * HA];
__device__ __align__(128) bf16 g_P  [(size_t)NH * M1 * NR];
__device__ __align__(128) bf16 g_O  [(size_t)M1 * HA];
__device__ __align__(128) bf16 g_Sh [(size_t)M1 * DIM];

// ---------------- PTX helpers ----------------
__device__ __forceinline__ uint32_t s2u(const void* p) {
    return (uint32_t)__cvta_generic_to_shared(p);
}
__device__ __forceinline__ void cp16(uint32_t d, const void* s) {
    asm volatile("cp.async.cg.shared.global [%0], [%1], 16;\n" :: "r"(d), "l"(s));
}
__device__ __forceinline__ void cp_commit() { asm volatile("cp.async.commit_group;\n" ::); }
template <int N>
__device__ __forceinline__ void cp_wait() { asm volatile("cp.async.wait_group %0;\n" :: "n"(N)); }

__device__ __forceinline__ void ldsm4(uint32_t& r0, uint32_t& r1, uint32_t& r2, uint32_t& r3, uint32_t a) {
    asm volatile("ldmatrix.sync.aligned.m8n8.x4.shared.b16 {%0,%1,%2,%3}, [%4];\n"
                 : "=r"(r0), "=r"(r1), "=r"(r2), "=r"(r3) : "r"(a));
}
__device__ __forceinline__ void ldsm4t(uint32_t& r0, uint32_t& r1, uint32_t& r2, uint32_t& r3, uint32_t a) {
    asm volatile("ldmatrix.sync.aligned.m8n8.x4.trans.shared.b16 {%0,%1,%2,%3}, [%4];\n"
                 : "=r"(r0), "=r"(r1), "=r"(r2), "=r"(r3) : "r"(a));
}
__device__ __forceinline__ void mma16816(float c[4],
                                         uint32_t a0, uint32_t a1, uint32_t a2, uint32_t a3,
                                         uint32_t b0, uint32_t b1) {
    asm volatile(
        "mma.sync.aligned.m16n8k16.row.col.f32.bf16.bf16.f32 "
        "{%0,%1,%2,%3}, {%4,%5,%6,%7}, {%8,%9}, {%0,%1,%2,%3};\n"
        : "+f"(c[0]), "+f"(c[1]), "+f"(c[2]), "+f"(c[3])
        : "r"(a0), "r"(a1), "r"(a2), "r"(a3), "r"(b0), "r"(b1));
}

// ---------------- generic bf16 GEMM: C = scale*(A@B) + bias ----------------
// 128x128 CTA tile, BK=32, 256 threads, 4-stage cp.async ring, 2 CTAs/SM.
constexpr int STAGES   = 4;
constexpr int A_ELEMS  = 128 * 40;          // padded A stage (rows 128, stride 40)
constexpr int B_ELEMS  = 32 * 136;          // padded B stage (rows 32, stride 136)
constexpr int ST_ELEMS = A_ELEMS + B_ELEMS; // 9472 elems = 18944 B
constexpr int GEMM_SMEM = STAGES * ST_ELEMS * 2;

__global__ __launch_bounds__(256, 2)
void gemm_kernel(const bf16* __restrict__ A, int lda, long long aZ,
                 const bf16* __restrict__ B, int ldb, long long bZ,
                 bf16* __restrict__ C, int ldc, long long cZ,
                 int K, const float* __restrict__ bias, float scale) {
    extern __shared__ bf16 sm[];
    typedef bf16 (*AsT)[40];
    typedef bf16 (*BsT)[136];

    int z = blockIdx.z;
    A += (size_t)z * aZ;  B += (size_t)z * bZ;  C += (size_t)z * cZ;

    const int row0 = blockIdx.y * 128, col0 = blockIdx.x * 128;
    const int tid = threadIdx.x, lane = tid & 31, w = tid >> 5;
    const int wm = w >> 2, wn = w & 3;              // 2 x 4 warp grid, 64x32 per warp

    const int ar = tid >> 1, ac = (tid & 1) * 16;   // A tile gmem->smem mapping
    const int br = tid >> 3, bc = (tid & 7) * 16;   // B tile

    const bf16* Ag = A + (size_t)(row0 + ar) * lda + ac;
    const bf16* Bg = B + (size_t)br * ldb + col0 + bc;

    uint32_t sA[STAGES], sB[STAGES];
    #pragma unroll
    for (int s = 0; s < STAGES; s++) {
        sA[s] = s2u(sm + s * ST_ELEMS + ar * 40 + ac);
        sB[s] = s2u(sm + s * ST_ELEMS + A_ELEMS + br * 136 + bc);
    }

    float acc[4][4][4];
    #pragma unroll
    for (int i = 0; i < 4; i++)
        #pragma unroll
        for (int j = 0; j < 4; j++)
            #pragma unroll
            for (int k = 0; k < 4; k++) acc[i][j][k] = 0.f;

    auto issue = [&](int c) {
        const int s = c & (STAGES - 1);
        const bf16* a = Ag + c * 32;
        cp16(sA[s],      a);
        cp16(sA[s] + 16, a + 8);
        const bf16* b = Bg + ((size_t)c * 32) * ldb;
        cp16(sB[s],      b);
        cp16(sB[s] + 16, b + 8);
        cp_commit();
    };

    const int tiles = K >> 5;
    issue(0); issue(1); issue(2);

    for (int kt = 0; kt < tiles; ++kt) {
        const int rem = tiles - 1 - kt;
        if (rem >= 2)      cp_wait<2>();
        else if (rem == 1) cp_wait<1>();
        else               cp_wait<0>();
        __syncthreads();
        if (kt + 3 < tiles) issue(kt + 3);

        const int buf = kt & (STAGES - 1);
        AsT As = (AsT)(sm + buf * ST_ELEMS);
        BsT Bs = (BsT)(sm + buf * ST_ELEMS + A_ELEMS);

        #pragma unroll
        for (int ks = 0; ks < 2; ++ks) {
            uint32_t a[4][4];
            #pragma unroll
            for (int mi = 0; mi < 4; ++mi) {
                uint32_t ad = s2u(&As[wm * 64 + mi * 16 + (lane & 15)]
                                     [ks * 16 + ((lane >> 4) << 3)]);
                ldsm4(a[mi][0], a[mi][1], a[mi][2], a[mi][3], ad);
            }
            uint32_t bq[2][4];
            #pragma unroll
            for (int bj = 0; bj < 2; ++bj) {
                int r = ks * 16 + (lane & 7) + (((lane >> 3) & 1) << 3);
                int c = wn * 32 + bj * 16 + ((lane >> 4) << 3);
                uint32_t bd = s2u(&Bs[r][c]);
                ldsm4t(bq[bj][0], bq[bj][1], bq[bj][2], bq[bj][3], bd);
            }
            #pragma unroll
            for (int mi = 0; mi < 4; ++mi)
                #pragma unroll
                for (int ni = 0; ni < 4; ++ni)
                    mma16816(acc[mi][ni],
                             a[mi][0], a[mi][1], a[mi][2], a[mi][3],
                             bq[ni >> 1][(ni & 1) * 2], bq[ni >> 1][(ni & 1) * 2 + 1]);
        }
    }

    // epilogue
    #pragma unroll
    for (int mi = 0; mi < 4; ++mi) {
        #pragma unroll
        for (int ni = 0; ni < 4; ++ni) {
            int r = row0 + wm * 64 + mi * 16 + (lane >> 2);
            int c = col0 + wn * 32 + ni * 8 + (lane & 3) * 2;
            float b0 = 0.f, b1 = 0.f;
            if (bias) { b0 = bias[c]; b1 = bias[c + 1]; }
            bf162 lo, hi;
            lo.x = __float2bfloat16(acc[mi][ni][0] * scale + b0);
            lo.y = __float2bfloat16(acc[mi][ni][1] * scale + b1);
            hi.x = __float2bfloat16(acc[mi][ni][2] * scale + b0);
            hi.y = __float2bfloat16(acc[mi][ni][3] * scale + b1);
            *(bf162*)(C + (size_t)r * ldc + c)       = lo;
            *(bf162*)(C + (size_t)(r + 8) * ldc + c) = hi;
        }
    }
}

// ---------------- packing kernels ----------------
__global__ void build_sf_kernel(const float* __restrict__ q,
                                const float* __restrict__ sa,
                                const float* __restrict__ si) {
    size_t i = (size_t)blockIdx.x * blockDim.x + threadIdx.x;
    size_t e = i * 4;
    int row = (int)(e >> 10);
    int d   = (int)(e & 1023);
    int b = row / 25, t = row - b * 25;
    const float* src; size_t off;
    if (t == 0)        { src = q;  off = (size_t)b * 1024; }
    else if (t <= 12)  { src = sa; off = ((size_t)b * 12 + (t - 1)) * 1024; }
    else               { src = si; off = ((size_t)b * 12 + (t - 13)) * 1024; }
    float4 f = *(const float4*)(src + off + d);
    bf162 lo, hi;
    lo.x = __float2bfloat16(f.x); lo.y = __float2bfloat16(f.y);
    hi.x = __float2bfloat16(f.z); hi.y = __float2bfloat16(f.w);
    bf162* dst = (bf162*)(g_Sf + e);
    dst[0] = lo; dst[1] = hi;
}

__global__ void cvt_kernel(bf16* __restrict__ dst, const float* __restrict__ src) {
    size_t i = (size_t)blockIdx.x * blockDim.x + threadIdx.x;
    float4 f = ((const float4*)src)[i];
    bf162 lo, hi;
    lo.x = __float2bfloat16(f.x); lo.y = __float2bfloat16(f.y);
    hi.x = __float2bfloat16(f.z); hi.y = __float2bfloat16(f.w);
    bf162* d = (bf162*)(dst + i * 4);
    d[0] = lo; d[1] = hi;
}

// K [NR][HA] -> Kt [HA][NR]
__global__ void transpose_kernel(const bf16* __restrict__ in, bf16* __restrict__ out) {
    __shared__ bf16 tile[32][33];
    int x0 = blockIdx.x * 32, y0 = blockIdx.y * 32;
    int tx = threadIdx.x, ty = threadIdx.y;
    for (int i = ty; i < 32; i += 8)
        tile[i][tx] = in[(size_t)(y0 + i) * HA + x0 + tx];
    __syncthreads();
    for (int i = ty; i < 32; i += 8)
        out[(size_t)(x0 + i) * NR + y0 + tx] = tile[tx][i];
}

// ---------------- softmax over rows of 2048, in place ----------------
__global__ __launch_bounds__(256)
void softmax_kernel(bf16* __restrict__ P) {
    size_t row = blockIdx.x;
    bf162* p = (bf162*)(P + row * (size_t)NR);
    int t = threadIdx.x, lane = t & 31, w = t >> 5;
    __shared__ float red[8];

    float v[8];
    float mx = -1e30f;
    #pragma unroll
    for (int i = 0; i < 4; i++) {
        bf162 h = p[t + i * 256];
        v[2 * i]     = __bfloat162float(h.x);
        v[2 * i + 1] = __bfloat162float(h.y);
        mx = fmaxf(mx, fmaxf(v[2 * i], v[2 * i + 1]));
    }
    #pragma unroll
    for (int o = 16; o; o >>= 1) mx = fmaxf(mx, __shfl_xor_sync(0xffffffffu, mx, o));
    if (lane == 0) red[w] = mx;
    __syncthreads();
    mx = red[0];
    #pragma unroll
    for (int i = 1; i < 8; i++) mx = fmaxf(mx, red[i]);

    float s = 0.f;
    #pragma unroll
    for (int i = 0; i < 8; i++) { v[i] = __expf(v[i] - mx); s += v[i]; }
    #pragma unroll
    for (int o = 16; o; o >>= 1) s += __shfl_xor_sync(0xffffffffu, s, o);
    __syncthreads();
    if (lane == 0) red[w] = s;
    __syncthreads();
    s = red[0];
    #pragma unroll
    for (int i = 1; i < 8; i++) s += red[i];
    float inv = 1.0f / s;

    #pragma unroll
    for (int i = 0; i < 4; i++) {
        bf162 h;
        h.x = __float2bfloat16(v[2 * i] * inv);
        h.y = __float2bfloat16(v[2 * i + 1] * inv);
        p[t + i * 256] = h;
    }
}

// ---------------- residual + scatter into output sections ----------------
__global__ void scatter_kernel(const float* __restrict__ q,
                               const float* __restrict__ sa,
                               const float* __restrict__ si,
                               float* __restrict__ out) {
    size_t i = (size_t)blockIdx.x * blockDim.x + threadIdx.x;
    if (i >= (size_t)M1 * DIM / 2) return;
    int row = (int)(i >> 9);
    int d   = (int)((i & 511) * 2);
    int b = row / 25, t = row - b * 25;
    const float* src; size_t off, base;
    if (t == 0)       { src = q;  off = (size_t)b * 1024;                   base = 0; }
    else if (t <= 12) { src = sa; off = ((size_t)b * 12 + (t - 1)) * 1024;  base = (size_t)BATCH * 1024; }
    else              { src = si; off = ((size_t)b * 12 + (t - 13)) * 1024; base = (size_t)BATCH * 1024 * 13; }
    float2 sv = *(const float2*)(src + off + d);
    bf162  h  = *(const bf162*)(g_Sh + (size_t)row * DIM + d);
    float2 o;
    o.x = sv.x + __bfloat162float(h.x);
    o.y = sv.y + __bfloat162float(h.y);
    *(float2*)(out + base + off + d) = o;
}

// ---------------- launch ----------------
extern "C" void kernel_launch(void* const* d_in, const int* in_sizes, int n_in,
                              void* d_out, int out_size) {
    const float* q   = (const float*)d_in[0];
    const float* sa  = (const float*)d_in[1];
    const float* si  = (const float*)d_in[2];
    const float* ref = (const float*)d_in[5];
    const float* Wq  = (const float*)d_in[6];
    const float* bq  = (const float*)d_in[7];
    const float* Wk  = (const float*)d_in[8];
    const float* bk  = (const float*)d_in[9];
    const float* Wv  = (const float*)d_in[10];
    const float* bv  = (const float*)d_in[11];
    const float* Wo  = (const float*)d_in[12];
    const float* bo  = (const float*)d_in[13];
    float* out = (float*)d_out;

    static bf16 *pSf = nullptr, *pRef, *pWq, *pWk, *pWv, *pWo,
                *pQ, *pK, *pKt, *pV, *pP, *pO, *pSh;
    if (!pSf) {
        cudaGetSymbolAddress((void**)&pSf,  g_Sf);
        cudaGetSymbolAddress((void**)&pRef, g_ref);
        cudaGetSymbolAddress((void**)&pWq,  g_Wq);
        cudaGetSymbolAddress((void**)&pWk,  g_Wk);
        cudaGetSymbolAddress((void**)&pWv,  g_Wv);
        cudaGetSymbolAddress((void**)&pWo,  g_Wo);
        cudaGetSymbolAddress((void**)&pQ,   g_Q);
        cudaGetSymbolAddress((void**)&pK,   g_K);
        cudaGetSymbolAddress((void**)&pKt,  g_Kt);
        cudaGetSymbolAddress((void**)&pV,   g_V);
        cudaGetSymbolAddress((void**)&pP,   g_P);
        cudaGetSymbolAddress((void**)&pO,   g_O);
        cudaGetSymbolAddress((void**)&pSh,  g_Sh);
        cudaFuncSetAttribute(gemm_kernel, cudaFuncAttributeMaxDynamicSharedMemorySize, GEMM_SMEM);
    }

    // 1) pack inputs to bf16
    build_sf_kernel<<<(M1 * DIM / 4) / 256, 256>>>(q, sa, si);
    cvt_kernel<<<((size_t)NR  * DIM / 4) / 256, 256>>>(pRef, ref);
    cvt_kernel<<<((size_t)DIM * HA  / 4) / 256, 256>>>(pWq, Wq);
    cvt_kernel<<<((size_t)DIM * HA  / 4) / 256, 256>>>(pWk, Wk);
    cvt_kernel<<<((size_t)DIM * HA  / 4) / 256, 256>>>(pWv, Wv);
    cvt_kernel<<<((size_t)HA  * DIM / 4) / 256, 256>>>(pWo, Wo);

    // 2) projections
    gemm_kernel<<<dim3(HA / 128, M1 / 128, 1), 256, GEMM_SMEM>>>(
        pSf, DIM, 0, pWq, HA, 0, pQ, HA, 0, DIM, bq, 1.0f);
    gemm_kernel<<<dim3(HA / 128, NR / 128, 1), 256, GEMM_SMEM>>>(
        pRef, DIM, 0, pWk, HA, 0, pK, HA, 0, DIM, bk, 1.0f);
    gemm_kernel<<<dim3(HA / 128, NR / 128, 1), 256, GEMM_SMEM>>>(
        pRef, DIM, 0, pWv, HA, 0, pV, HA, 0, DIM, bv, 1.0f);

    // 3) K -> Kt so scores GEMM is NN
    transpose_kernel<<<dim3(HA / 32, NR / 32), dim3(32, 8)>>>(pK, pKt);

    // 4) scores[h] = BETA * Q_h @ Kt_h   (batched over heads via z)
    gemm_kernel<<<dim3(NR / 128, M1 / 128, NH), 256, GEMM_SMEM>>>(
        pQ, HA, HD,
        pKt, NR, (long long)HD * NR,
        pP, NR, (long long)M1 * NR,
        HD, nullptr, BETA_F);

    // 5) softmax rows
    softmax_kernel<<<NH * M1, 256>>>(pP);

    // 6) out[h] = P_h @ V_h
    gemm_kernel<<<dim3(HD / 128, M1 / 128, NH), 256, GEMM_SMEM>>>(
        pP, NR, (long long)M1 * NR,
        pV, HA, HD,
        pO, HA, HD,
        NR, nullptr, 1.0f);

    // 7) Sh = O @ Wo + bo
    gemm_kernel<<<dim3(DIM / 128, M1 / 128, 1), 256, GEMM_SMEM>>>(
        pO, HA, 0, pWo, DIM, 0, pSh, DIM, 0, HA, bo, 1.0f);

    // 8) residual + scatter into (query, actives, inactives) sections
    scatter_kernel<<<(M1 * DIM / 2 + 255) / 256, 256>>>(q, sa, si, out);
}

// round 5
// speedup vs baseline: 1.6256x; 1.1530x over previous
#include <cuda_runtime.h>
#include <cuda_bf16.h>
#include <stdint.h>

using bf16  = __nv_bfloat16;
using bf162 = __nv_bfloat162;

// ---------------- problem constants ----------------
constexpr int BATCH = 256;
constexpr int M1    = 6400;        // 256 * 25 rows
constexpr int DIM   = 1024;
constexpr int HA    = 4096;        // H*A
constexpr int NR    = 2048;
constexpr int NH    = 8;
constexpr int HD    = 512;
constexpr float BETA_F = 0.044194173824159216f;

// ---------------- device scratch (static, allocation-free) ----------------
__device__ __align__(128) bf16 g_Sf [(size_t)M1 * DIM];
__device__ __align__(128) bf16 g_ref[(size_t)NR * DIM];
__device__ __align__(128) bf16 g_Wq [(size_t)DIM * HA];
__device__ __align__(128) bf16 g_Wk [(size_t)DIM * HA];
__device__ __align__(128) bf16 g_Wv [(size_t)DIM * HA];
__device__ __align__(128) bf16 g_Wo [(size_t)HA * DIM];
__device__ __align__(128) bf16 g_Q  [(size_t)M1 * HA];
__device__ __align__(128) bf16 g_K  [(size_t)NR * HA];
__device__ __align__(128) bf16 g_Kt [(size_t)HA * NR];
__device__ __align__(128) bf16 g_V  [(size_t)NR * HA];
__device__ __align__(128) bf16 g_P  [(size_t)NH * M1 * NR];
__device__ __align__(128) bf16 g_O  [(size_t)M1 * HA];
__device__ __align__(128) bf16 g_Sh [(size_t)M1 * DIM];

// ---------------- PTX helpers ----------------
__device__ __forceinline__ uint32_t s2u(const void* p) {
    return (uint32_t)__cvta_generic_to_shared(p);
}
__device__ __forceinline__ void cp16(uint32_t d, const void* s) {
    asm volatile("cp.async.cg.shared.global [%0], [%1], 16;\n" :: "r"(d), "l"(s));
}
__device__ __forceinline__ void cp_commit() { asm volatile("cp.async.commit_group;\n" ::); }
template <int N>
__device__ __forceinline__ void cp_wait() { asm volatile("cp.async.wait_group %0;\n" :: "n"(N)); }

__device__ __forceinline__ void ldsm4(uint32_t& r0, uint32_t& r1, uint32_t& r2, uint32_t& r3, uint32_t a) {
    asm volatile("ldmatrix.sync.aligned.m8n8.x4.shared.b16 {%0,%1,%2,%3}, [%4];\n"
                 : "=r"(r0), "=r"(r1), "=r"(r2), "=r"(r3) : "r"(a));
}
__device__ __forceinline__ void ldsm4t(uint32_t& r0, uint32_t& r1, uint32_t& r2, uint32_t& r3, uint32_t a) {
    asm volatile("ldmatrix.sync.aligned.m8n8.x4.trans.shared.b16 {%0,%1,%2,%3}, [%4];\n"
                 : "=r"(r0), "=r"(r1), "=r"(r2), "=r"(r3) : "r"(a));
}
__device__ __forceinline__ void mma16816(float c[4],
                                         uint32_t a0, uint32_t a1, uint32_t a2, uint32_t a3,
                                         uint32_t b0, uint32_t b1) {
    asm volatile(
        "mma.sync.aligned.m16n8k16.row.col.f32.bf16.bf16.f32 "
        "{%0,%1,%2,%3}, {%4,%5,%6,%7}, {%8,%9}, {%0,%1,%2,%3};\n"
        : "+f"(c[0]), "+f"(c[1]), "+f"(c[2]), "+f"(c[3])
        : "r"(a0), "r"(a1), "r"(a2), "r"(a3), "r"(b0), "r"(b1));
}

// ---------------- generic bf16 GEMM: C = scale*(A@B) + bias ----------------
// 128x128 CTA tile, BK=64, 256 threads, 3-stage cp.async ring, 2 CTAs/SM.
constexpr int STAGES   = 3;
constexpr int A_STRIDE = 72;                 // 144B row stride (16 mod 128 -> conflict-free)
constexpr int B_STRIDE = 136;                // 272B row stride
constexpr int A_ELEMS  = 128 * A_STRIDE;     // 9216
constexpr int B_ELEMS  = 64 * B_STRIDE;      // 8704
constexpr int ST_ELEMS = A_ELEMS + B_ELEMS;  // 17920 el = 35840 B
constexpr int GEMM_SMEM = STAGES * ST_ELEMS * 2;   // 107520 B

__global__ __launch_bounds__(256, 2)
void gemm_kernel(const bf16* __restrict__ A, int lda, long long aZ,
                 const bf16* __restrict__ B, int ldb, long long bZ,
                 bf16* __restrict__ C, int ldc, long long cZ,
                 int K, const float* __restrict__ bias, float scale) {
    extern __shared__ bf16 sm[];
    typedef bf16 (*AsT)[A_STRIDE];
    typedef bf16 (*BsT)[B_STRIDE];

    int z = blockIdx.z;
    A += (size_t)z * aZ;  B += (size_t)z * bZ;  C += (size_t)z * cZ;

    const int row0 = blockIdx.y * 128, col0 = blockIdx.x * 128;
    const int tid = threadIdx.x, lane = tid & 31, w = tid >> 5;
    const int wm = w >> 2, wn = w & 3;              // 2 x 4 warp grid, 64x32 per warp

    // gmem->smem copy mapping (per-thread 4 A segs + 4 B segs of 16B)
    // A tile: 128 rows x 64 cols (128B/row = 8 segs); B tile: 64 rows x 128 cols (16 segs)
    int aRow[4], aCol[4], bRow[4], bCol[4];
    #pragma unroll
    for (int i = 0; i < 4; i++) {
        int seg = tid + i * 256;
        aRow[i] = seg >> 3;  aCol[i] = (seg & 7) * 8;
        bRow[i] = seg >> 4;  bCol[i] = (seg & 15) * 8;
    }

    float acc[4][4][4];
    #pragma unroll
    for (int i = 0; i < 4; i++)
        #pragma unroll
        for (int j = 0; j < 4; j++)
            #pragma unroll
            for (int k = 0; k < 4; k++) acc[i][j][k] = 0.f;

    auto issue = [&](int c) {
        const int s  = c % STAGES;
        bf16* base   = sm + s * ST_ELEMS;
        const bf16* Ab = A + (size_t)row0 * lda + c * 64;
        #pragma unroll
        for (int i = 0; i < 4; i++)
            cp16(s2u(base + aRow[i] * A_STRIDE + aCol[i]),
                 Ab + (size_t)aRow[i] * lda + aCol[i]);
        const bf16* Bb = B + ((size_t)c * 64) * ldb + col0;
        #pragma unroll
        for (int i = 0; i < 4; i++)
            cp16(s2u(base + A_ELEMS + bRow[i] * B_STRIDE + bCol[i]),
                 Bb + (size_t)bRow[i] * ldb + bCol[i]);
        cp_commit();
    };

    const int tiles = K >> 6;
    issue(0); issue(1);

    for (int kt = 0; kt < tiles; ++kt) {
        if (kt < tiles - 1) cp_wait<1>();
        else                cp_wait<0>();
        __syncthreads();
        if (kt + 2 < tiles) issue(kt + 2);

        const int buf = kt % STAGES;
        AsT As = (AsT)(sm + buf * ST_ELEMS);
        BsT Bs = (BsT)(sm + buf * ST_ELEMS + A_ELEMS);

        #pragma unroll
        for (int ks = 0; ks < 4; ++ks) {
            uint32_t a[4][4];
            #pragma unroll
            for (int mi = 0; mi < 4; ++mi) {
                uint32_t ad = s2u(&As[wm * 64 + mi * 16 + (lane & 15)]
                                     [ks * 16 + ((lane >> 4) << 3)]);
                ldsm4(a[mi][0], a[mi][1], a[mi][2], a[mi][3], ad);
            }
            uint32_t bq[2][4];
            #pragma unroll
            for (int bj = 0; bj < 2; ++bj) {
                int r = ks * 16 + (lane & 7) + (((lane >> 3) & 1) << 3);
                int c = wn * 32 + bj * 16 + ((lane >> 4) << 3);
                uint32_t bd = s2u(&Bs[r][c]);
                ldsm4t(bq[bj][0], bq[bj][1], bq[bj][2], bq[bj][3], bd);
            }
            #pragma unroll
            for (int mi = 0; mi < 4; ++mi)
                #pragma unroll
                for (int ni = 0; ni < 4; ++ni)
                    mma16816(acc[mi][ni],
                             a[mi][0], a[mi][1], a[mi][2], a[mi][3],
                             bq[ni >> 1][(ni & 1) * 2], bq[ni >> 1][(ni & 1) * 2 + 1]);
        }
        __syncthreads();
    }

    // epilogue
    #pragma unroll
    for (int mi = 0; mi < 4; ++mi) {
        #pragma unroll
        for (int ni = 0; ni < 4; ++ni) {
            int r = row0 + wm * 64 + mi * 16 + (lane >> 2);
            int c = col0 + wn * 32 + ni * 8 + (lane & 3) * 2;
            float b0 = 0.f, b1 = 0.f;
            if (bias) { b0 = bias[c]; b1 = bias[c + 1]; }
            bf162 lo, hi;
            lo.x = __float2bfloat16(acc[mi][ni][0] * scale + b0);
            lo.y = __float2bfloat16(acc[mi][ni][1] * scale + b1);
            hi.x = __float2bfloat16(acc[mi][ni][2] * scale + b0);
            hi.y = __float2bfloat16(acc[mi][ni][3] * scale + b1);
            *(bf162*)(C + (size_t)r * ldc + c)       = lo;
            *(bf162*)(C + (size_t)(r + 8) * ldc + c) = hi;
        }
    }
}

// ---------------- packing kernels ----------------
__global__ void build_sf_kernel(const float* __restrict__ q,
                                const float* __restrict__ sa,
                                const float* __restrict__ si) {
    size_t i = (size_t)blockIdx.x * blockDim.x + threadIdx.x;
    size_t e = i * 4;
    int row = (int)(e >> 10);
    int d   = (int)(e & 1023);
    int b = row / 25, t = row - b * 25;
    const float* src; size_t off;
    if (t == 0)        { src = q;  off = (size_t)b * 1024; }
    else if (t <= 12)  { src = sa; off = ((size_t)b * 12 + (t - 1)) * 1024; }
    else               { src = si; off = ((size_t)b * 12 + (t - 13)) * 1024; }
    float4 f = *(const float4*)(src + off + d);
    bf162 lo, hi;
    lo.x = __float2bfloat16(f.x); lo.y = __float2bfloat16(f.y);
    hi.x = __float2bfloat16(f.z); hi.y = __float2bfloat16(f.w);
    bf162* dst = (bf162*)(g_Sf + e);
    dst[0] = lo; dst[1] = hi;
}

__global__ void cvt_kernel(bf16* __restrict__ dst, const float* __restrict__ src) {
    size_t i = (size_t)blockIdx.x * blockDim.x + threadIdx.x;
    float4 f = ((const float4*)src)[i];
    bf162 lo, hi;
    lo.x = __float2bfloat16(f.x); lo.y = __float2bfloat16(f.y);
    hi.x = __float2bfloat16(f.z); hi.y = __float2bfloat16(f.w);
    bf162* d = (bf162*)(dst + i * 4);
    d[0] = lo; d[1] = hi;
}

// all four weight matrices in one launch (each 4M elements)
constexpr size_t WELEMS = (size_t)DIM * HA;     // 4M
__global__ void cvt_weights_kernel(const float* __restrict__ wq,
                                   const float* __restrict__ wk,
                                   const float* __restrict__ wv,
                                   const float* __restrict__ wo) {
    size_t i = (size_t)blockIdx.x * blockDim.x + threadIdx.x;  // float4 units
    size_t which = i / (WELEMS / 4);
    size_t idx   = i % (WELEMS / 4);
    const float* src;
    bf16* dst;
    if      (which == 0) { src = wq; dst = g_Wq; }
    else if (which == 1) { src = wk; dst = g_Wk; }
    else if (which == 2) { src = wv; dst = g_Wv; }
    else                 { src = wo; dst = g_Wo; }
    float4 f = ((const float4*)src)[idx];
    bf162 lo, hi;
    lo.x = __float2bfloat16(f.x); lo.y = __float2bfloat16(f.y);
    hi.x = __float2bfloat16(f.z); hi.y = __float2bfloat16(f.w);
    bf162* d = (bf162*)(dst + idx * 4);
    d[0] = lo; d[1] = hi;
}

// K [NR][HA] -> Kt [HA][NR]
__global__ void transpose_kernel(const bf16* __restrict__ in, bf16* __restrict__ out) {
    __shared__ bf16 tile[32][33];
    int x0 = blockIdx.x * 32, y0 = blockIdx.y * 32;
    int tx = threadIdx.x, ty = threadIdx.y;
    for (int i = ty; i < 32; i += 8)
        tile[i][tx] = in[(size_t)(y0 + i) * HA + x0 + tx];
    __syncthreads();
    for (int i = ty; i < 32; i += 8)
        out[(size_t)(x0 + i) * NR + y0 + tx] = tile[tx][i];
}

// ---------------- softmax over rows of 2048, in place ----------------
__global__ __launch_bounds__(256)
void softmax_kernel(bf16* __restrict__ P) {
    size_t row = blockIdx.x;
    bf162* p = (bf162*)(P + row * (size_t)NR);
    int t = threadIdx.x, lane = t & 31, w = t >> 5;
    __shared__ float red[8];

    float v[8];
    float mx = -1e30f;
    #pragma unroll
    for (int i = 0; i < 4; i++) {
        bf162 h = p[t + i * 256];
        v[2 * i]     = __bfloat162float(h.x);
        v[2 * i + 1] = __bfloat162float(h.y);
        mx = fmaxf(mx, fmaxf(v[2 * i], v[2 * i + 1]));
    }
    #pragma unroll
    for (int o = 16; o; o >>= 1) mx = fmaxf(mx, __shfl_xor_sync(0xffffffffu, mx, o));
    if (lane == 0) red[w] = mx;
    __syncthreads();
    mx = red[0];
    #pragma unroll
    for (int i = 1; i < 8; i++) mx = fmaxf(mx, red[i]);

    float s = 0.f;
    #pragma unroll
    for (int i = 0; i < 8; i++) { v[i] = __expf(v[i] - mx); s += v[i]; }
    #pragma unroll
    for (int o = 16; o; o >>= 1) s += __shfl_xor_sync(0xffffffffu, s, o);
    __syncthreads();
    if (lane == 0) red[w] = s;
    __syncthreads();
    s = red[0];
    #pragma unroll
    for (int i = 1; i < 8; i++) s += red[i];
    float inv = 1.0f / s;

    #pragma unroll
    for (int i = 0; i < 4; i++) {
        bf162 h;
        h.x = __float2bfloat16(v[2 * i] * inv);
        h.y = __float2bfloat16(v[2 * i + 1] * inv);
        p[t + i * 256] = h;
    }
}

// ---------------- residual + scatter into output sections ----------------
__global__ void scatter_kernel(const float* __restrict__ q,
                               const float* __restrict__ sa,
                               const float* __restrict__ si,
                               float* __restrict__ out) {
    size_t i = (size_t)blockIdx.x * blockDim.x + threadIdx.x;
    if (i >= (size_t)M1 * DIM / 2) return;
    int row = (int)(i >> 9);
    int d   = (int)((i & 511) * 2);
    int b = row / 25, t = row - b * 25;
    const float* src; size_t off, base;
    if (t == 0)       { src = q;  off = (size_t)b * 1024;                   base = 0; }
    else if (t <= 12) { src = sa; off = ((size_t)b * 12 + (t - 1)) * 1024;  base = (size_t)BATCH * 1024; }
    else              { src = si; off = ((size_t)b * 12 + (t - 13)) * 1024; base = (size_t)BATCH * 1024 * 13; }
    float2 sv = *(const float2*)(src + off + d);
    bf162  h  = *(const bf162*)(g_Sh + (size_t)row * DIM + d);
    float2 o;
    o.x = sv.x + __bfloat162float(h.x);
    o.y = sv.y + __bfloat162float(h.y);
    *(float2*)(out + base + off + d) = o;
}

// ---------------- launch ----------------
extern "C" void kernel_launch(void* const* d_in, const int* in_sizes, int n_in,
                              void* d_out, int out_size) {
    const float* q   = (const float*)d_in[0];
    const float* sa  = (const float*)d_in[1];
    const float* si  = (const float*)d_in[2];
    const float* ref = (const float*)d_in[5];
    const float* Wq  = (const float*)d_in[6];
    const float* bq  = (const float*)d_in[7];
    const float* Wk  = (const float*)d_in[8];
    const float* bk  = (const float*)d_in[9];
    const float* Wv  = (const float*)d_in[10];
    const float* bv  = (const float*)d_in[11];
    const float* Wo  = (const float*)d_in[12];
    const float* bo  = (const float*)d_in[13];
    float* out = (float*)d_out;

    static bf16 *pSf = nullptr, *pRef, *pWq, *pWk, *pWv, *pWo,
                *pQ, *pK, *pKt, *pV, *pP, *pO, *pSh;
    if (!pSf) {
        cudaGetSymbolAddress((void**)&pSf,  g_Sf);
        cudaGetSymbolAddress((void**)&pRef, g_ref);
        cudaGetSymbolAddress((void**)&pWq,  g_Wq);
        cudaGetSymbolAddress((void**)&pWk,  g_Wk);
        cudaGetSymbolAddress((void**)&pWv,  g_Wv);
        cudaGetSymbolAddress((void**)&pWo,  g_Wo);
        cudaGetSymbolAddress((void**)&pQ,   g_Q);
        cudaGetSymbolAddress((void**)&pK,   g_K);
        cudaGetSymbolAddress((void**)&pKt,  g_Kt);
        cudaGetSymbolAddress((void**)&pV,   g_V);
        cudaGetSymbolAddress((void**)&pP,   g_P);
        cudaGetSymbolAddress((void**)&pO,   g_O);
        cudaGetSymbolAddress((void**)&pSh,  g_Sh);
        cudaFuncSetAttribute(gemm_kernel, cudaFuncAttributeMaxDynamicSharedMemorySize, GEMM_SMEM);
    }

    // launches 0-2: packing (ncu -s 5 window now lands on a GEMM)
    build_sf_kernel<<<(M1 * DIM / 4) / 256, 256>>>(q, sa, si);
    cvt_kernel<<<((size_t)NR * DIM / 4) / 256, 256>>>(pRef, ref);
    cvt_weights_kernel<<<(4 * WELEMS / 4) / 256, 256>>>(Wq, Wk, Wv, Wo);

    // launches 3-5: projections (launch 5 = V projection gets profiled)
    gemm_kernel<<<dim3(HA / 128, M1 / 128, 1), 256, GEMM_SMEM>>>(
        pSf, DIM, 0, pWq, HA, 0, pQ, HA, 0, DIM, bq, 1.0f);
    gemm_kernel<<<dim3(HA / 128, NR / 128, 1), 256, GEMM_SMEM>>>(
        pRef, DIM, 0, pWk, HA, 0, pK, HA, 0, DIM, bk, 1.0f);
    gemm_kernel<<<dim3(HA / 128, NR / 128, 1), 256, GEMM_SMEM>>>(
        pRef, DIM, 0, pWv, HA, 0, pV, HA, 0, DIM, bv, 1.0f);

    // K -> Kt so scores GEMM is NN
    transpose_kernel<<<dim3(HA / 32, NR / 32), dim3(32, 8)>>>(pK, pKt);

    // scores[h] = BETA * Q_h @ Kt_h   (batched over heads via z)
    gemm_kernel<<<dim3(NR / 128, M1 / 128, NH), 256, GEMM_SMEM>>>(
        pQ, HA, HD,
        pKt, NR, (long long)HD * NR,
        pP, NR, (long long)M1 * NR,
        HD, nullptr, BETA_F);

    // softmax rows
    softmax_kernel<<<NH * M1, 256>>>(pP);

    // out[h] = P_h @ V_h
    gemm_kernel<<<dim3(HD / 128, M1 / 128, NH), 256, GEMM_SMEM>>>(
        pP, NR, (long long)M1 * NR,
        pV, HA, HD,
        pO, HA, HD,
        NR, nullptr, 1.0f);

    // Sh = O @ Wo + bo
    gemm_kernel<<<dim3(DIM / 128, M1 / 128, 1), 256, GEMM_SMEM>>>(
        pO, HA, 0, pWo, DIM, 0, pSh, DIM, 0, HA, bo, 1.0f);

    // residual + scatter into (query, actives, inactives) sections
    scatter_kernel<<<(M1 * DIM / 2 + 255) / 256, 256>>>(q, sa, si, out);
}

// round 6
// speedup vs baseline: 1.6856x; 1.0369x over previous
#include <cuda_runtime.h>
#include <cuda_bf16.h>
#include <stdint.h>

using bf16  = __nv_bfloat16;
using bf162 = __nv_bfloat162;

// ---------------- problem constants ----------------
constexpr int BATCH = 256;
constexpr int M1    = 6400;        // 256 * 25 rows
constexpr int DIM   = 1024;
constexpr int HA    = 4096;        // H*A
constexpr int NR    = 2048;
constexpr int NH    = 8;
constexpr int HD    = 512;
constexpr float BETA_F = 0.044194173824159216f;

// ---------------- device scratch (static, allocation-free) ----------------
__device__ __align__(128) bf16 g_Sf [(size_t)M1 * DIM];
__device__ __align__(128) bf16 g_ref[(size_t)NR * DIM];
__device__ __align__(128) bf16 g_Wq [(size_t)DIM * HA];
__device__ __align__(128) bf16 g_Wk [(size_t)DIM * HA];
__device__ __align__(128) bf16 g_Wv [(size_t)DIM * HA];
__device__ __align__(128) bf16 g_Wo [(size_t)HA * DIM];
__device__ __align__(128) bf16 g_Q  [(size_t)M1 * HA];
__device__ __align__(128) bf16 g_K  [(size_t)NR * HA];
__device__ __align__(128) bf16 g_V  [(size_t)NR * HA];
__device__ __align__(128) bf16 g_P  [(size_t)NH * M1 * NR];
__device__ __align__(128) bf16 g_O  [(size_t)M1 * HA];
__device__ __align__(128) bf16 g_Sh [(size_t)M1 * DIM];

// ---------------- PTX helpers ----------------
__device__ __forceinline__ uint32_t s2u(const void* p) {
    return (uint32_t)__cvta_generic_to_shared(p);
}
__device__ __forceinline__ void cp16(uint32_t d, const void* s) {
    asm volatile("cp.async.cg.shared.global [%0], [%1], 16;\n" :: "r"(d), "l"(s));
}
__device__ __forceinline__ void cp_commit() { asm volatile("cp.async.commit_group;\n" ::); }
template <int N>
__device__ __forceinline__ void cp_wait() { asm volatile("cp.async.wait_group %0;\n" :: "n"(N)); }

__device__ __forceinline__ void ldsm4(uint32_t& r0, uint32_t& r1, uint32_t& r2, uint32_t& r3, uint32_t a) {
    asm volatile("ldmatrix.sync.aligned.m8n8.x4.shared.b16 {%0,%1,%2,%3}, [%4];\n"
                 : "=r"(r0), "=r"(r1), "=r"(r2), "=r"(r3) : "r"(a));
}
__device__ __forceinline__ void ldsm4t(uint32_t& r0, uint32_t& r1, uint32_t& r2, uint32_t& r3, uint32_t a) {
    asm volatile("ldmatrix.sync.aligned.m8n8.x4.trans.shared.b16 {%0,%1,%2,%3}, [%4];\n"
                 : "=r"(r0), "=r"(r1), "=r"(r2), "=r"(r3) : "r"(a));
}
__device__ __forceinline__ void mma16816(float c[4],
                                         uint32_t a0, uint32_t a1, uint32_t a2, uint32_t a3,
                                         uint32_t b0, uint32_t b1) {
    asm volatile(
        "mma.sync.aligned.m16n8k16.row.col.f32.bf16.bf16.f32 "
        "{%0,%1,%2,%3}, {%4,%5,%6,%7}, {%8,%9}, {%0,%1,%2,%3};\n"
        : "+f"(c[0]), "+f"(c[1]), "+f"(c[2]), "+f"(c[3])
        : "r"(a0), "r"(a1), "r"(a2), "r"(a3), "r"(b0), "r"(b1));
}

// ---------------- generic bf16 GEMM ----------------
// BT=false: C = scale*(A@B)+bias,   A [M,K] (lda), B [K,N] (ldb)   — trans ldsm for B
// BT=true : C = scale*(A@B^T)+bias, A [M,K] (lda), B [N,K] (ldb)   — non-trans ldsm for B
// 128x128 CTA tile, BK=64, 256 threads, 3-stage cp.async ring, single sync/ktile, 2 CTAs/SM.
constexpr int STAGES    = 3;
constexpr int A_STRIDE  = 72;                  // 144B row stride (16 mod 128 -> conflict-free)
constexpr int BN_STRIDE = 136;                 // NN mode: 64 rows x 136
constexpr int BT_STRIDE = 72;                  // BT mode: 128 rows x 72
constexpr int A_ELEMS   = 128 * A_STRIDE;      // 9216
constexpr int B_ELEMS   = 128 * 72;            // 9216 (max of 64*136=8704, 128*72=9216)
constexpr int ST_ELEMS  = A_ELEMS + B_ELEMS;   // 18432 el = 36864 B
constexpr int GEMM_SMEM = STAGES * ST_ELEMS * 2;   // 110592 B

template <bool BT>
__global__ __launch_bounds__(256, 2)
void gemm_kernel(const bf16* __restrict__ A, int lda, long long aZ,
                 const bf16* __restrict__ B, int ldb, long long bZ,
                 bf16* __restrict__ C, int ldc, long long cZ,
                 int K, const float* __restrict__ bias, float scale) {
    extern __shared__ bf16 sm[];
    typedef bf16 (*AsT)[A_STRIDE];
    typedef bf16 (*BnT)[BN_STRIDE];
    typedef bf16 (*BtT)[BT_STRIDE];

    int z = blockIdx.z;
    A += (size_t)z * aZ;  B += (size_t)z * bZ;  C += (size_t)z * cZ;

    const int row0 = blockIdx.y * 128, col0 = blockIdx.x * 128;
    const int tid = threadIdx.x, lane = tid & 31, w = tid >> 5;
    const int wm = w >> 2, wn = w & 3;              // 2 x 4 warp grid, 64x32 per warp

    // gmem->smem mapping: per-thread 4 A segs + 4 B segs of 16B
    int aRow[4], aCol[4], bRow[4], bCol[4];
    #pragma unroll
    for (int i = 0; i < 4; i++) {
        int seg = tid + i * 256;
        aRow[i] = seg >> 3;  aCol[i] = (seg & 7) * 8;
        if (BT) { bRow[i] = seg >> 3;  bCol[i] = (seg & 7) * 8; }     // 128 x 64
        else    { bRow[i] = seg >> 4;  bCol[i] = (seg & 15) * 8; }    // 64 x 128
    }

    float acc[4][4][4];
    #pragma unroll
    for (int i = 0; i < 4; i++)
        #pragma unroll
        for (int j = 0; j < 4; j++)
            #pragma unroll
            for (int k = 0; k < 4; k++) acc[i][j][k] = 0.f;

    auto issue = [&](int c) {
        const int s  = c % STAGES;
        bf16* base   = sm + s * ST_ELEMS;
        const bf16* Ab = A + (size_t)row0 * lda + c * 64;
        #pragma unroll
        for (int i = 0; i < 4; i++)
            cp16(s2u(base + aRow[i] * A_STRIDE + aCol[i]),
                 Ab + (size_t)aRow[i] * lda + aCol[i]);
        if (BT) {
            const bf16* Bb = B + (size_t)col0 * ldb + c * 64;   // rows = n, cols = k
            #pragma unroll
            for (int i = 0; i < 4; i++)
                cp16(s2u(base + A_ELEMS + bRow[i] * BT_STRIDE + bCol[i]),
                     Bb + (size_t)bRow[i] * ldb + bCol[i]);
        } else {
            const bf16* Bb = B + ((size_t)c * 64) * ldb + col0; // rows = k, cols = n
            #pragma unroll
            for (int i = 0; i < 4; i++)
                cp16(s2u(base + A_ELEMS + bRow[i] * BN_STRIDE + bCol[i]),
                     Bb + (size_t)bRow[i] * ldb + bCol[i]);
        }
        cp_commit();
    };

    const int tiles = K >> 6;
    issue(0); issue(1);

    for (int kt = 0; kt < tiles; ++kt) {
        if (kt < tiles - 1) cp_wait<1>();
        else                cp_wait<0>();
        __syncthreads();                 // single barrier per k-tile
        if (kt + 2 < tiles) issue(kt + 2);

        const int buf = kt % STAGES;
        AsT As = (AsT)(sm + buf * ST_ELEMS);

        #pragma unroll
        for (int ks = 0; ks < 4; ++ks) {
            uint32_t a[4][4];
            #pragma unroll
            for (int mi = 0; mi < 4; ++mi) {
                uint32_t ad = s2u(&As[wm * 64 + mi * 16 + (lane & 15)]
                                     [ks * 16 + ((lane >> 4) << 3)]);
                ldsm4(a[mi][0], a[mi][1], a[mi][2], a[mi][3], ad);
            }
            uint32_t bq[2][4];
            if (BT) {
                BtT Bs = (BtT)(sm + buf * ST_ELEMS + A_ELEMS);
                #pragma unroll
                for (int bj = 0; bj < 2; ++bj) {
                    int r = wn * 32 + bj * 16 + ((lane >> 4) << 3) + (lane & 7);
                    int c = ks * 16 + (((lane >> 3) & 1) << 3);
                    ldsm4(bq[bj][0], bq[bj][1], bq[bj][2], bq[bj][3], s2u(&Bs[r][c]));
                }
            } else {
                BnT Bs = (BnT)(sm + buf * ST_ELEMS + A_ELEMS);
                #pragma unroll
                for (int bj = 0; bj < 2; ++bj) {
                    int r = ks * 16 + (lane & 7) + (((lane >> 3) & 1) << 3);
                    int c = wn * 32 + bj * 16 + ((lane >> 4) << 3);
                    ldsm4t(bq[bj][0], bq[bj][1], bq[bj][2], bq[bj][3], s2u(&Bs[r][c]));
                }
            }
            #pragma unroll
            for (int mi = 0; mi < 4; ++mi)
                #pragma unroll
                for (int ni = 0; ni < 4; ++ni)
                    mma16816(acc[mi][ni],
                             a[mi][0], a[mi][1], a[mi][2], a[mi][3],
                             bq[ni >> 1][(ni & 1) * 2], bq[ni >> 1][(ni & 1) * 2 + 1]);
        }
    }

    // epilogue
    #pragma unroll
    for (int mi = 0; mi < 4; ++mi) {
        #pragma unroll
        for (int ni = 0; ni < 4; ++ni) {
            int r = row0 + wm * 64 + mi * 16 + (lane >> 2);
            int c = col0 + wn * 32 + ni * 8 + (lane & 3) * 2;
            float b0 = 0.f, b1 = 0.f;
            if (bias) { b0 = bias[c]; b1 = bias[c + 1]; }
            bf162 lo, hi;
            lo.x = __float2bfloat16(acc[mi][ni][0] * scale + b0);
            lo.y = __float2bfloat16(acc[mi][ni][1] * scale + b1);
            hi.x = __float2bfloat16(acc[mi][ni][2] * scale + b0);
            hi.y = __float2bfloat16(acc[mi][ni][3] * scale + b1);
            *(bf162*)(C + (size_t)r * ldc + c)       = lo;
            *(bf162*)(C + (size_t)(r + 8) * ldc + c) = hi;
        }
    }
}

// ---------------- packing kernels ----------------
__global__ void build_sf_kernel(const float* __restrict__ q,
                                const float* __restrict__ sa,
                                const float* __restrict__ si) {
    size_t i = (size_t)blockIdx.x * blockDim.x + threadIdx.x;
    size_t e = i * 4;
    int row = (int)(e >> 10);
    int d   = (int)(e & 1023);
    int b = row / 25, t = row - b * 25;
    const float* src; size_t off;
    if (t == 0)        { src = q;  off = (size_t)b * 1024; }
    else if (t <= 12)  { src = sa; off = ((size_t)b * 12 + (t - 1)) * 1024; }
    else               { src = si; off = ((size_t)b * 12 + (t - 13)) * 1024; }
    float4 f = *(const float4*)(src + off + d);
    bf162 lo, hi;
    lo.x = __float2bfloat16(f.x); lo.y = __float2bfloat16(f.y);
    hi.x = __float2bfloat16(f.z); hi.y = __float2bfloat16(f.w);
    bf162* dst = (bf162*)(g_Sf + e);
    dst[0] = lo; dst[1] = hi;
}

__global__ void cvt_kernel(bf16* __restrict__ dst, const float* __restrict__ src) {
    size_t i = (size_t)blockIdx.x * blockDim.x + threadIdx.x;
    float4 f = ((const float4*)src)[i];
    bf162 lo, hi;
    lo.x = __float2bfloat16(f.x); lo.y = __float2bfloat16(f.y);
    hi.x = __float2bfloat16(f.z); hi.y = __float2bfloat16(f.w);
    bf162* d = (bf162*)(dst + i * 4);
    d[0] = lo; d[1] = hi;
}

// all four weight matrices in one launch (each 4M elements)
constexpr size_t WELEMS = (size_t)DIM * HA;     // 4M
__global__ void cvt_weights_kernel(const float* __restrict__ wq,
                                   const float* __restrict__ wk,
                                   const float* __restrict__ wv,
                                   const float* __restrict__ wo) {
    size_t i = (size_t)blockIdx.x * blockDim.x + threadIdx.x;  // float4 units
    size_t which = i / (WELEMS / 4);
    size_t idx   = i % (WELEMS / 4);
    const float* src;
    bf16* dst;
    if      (which == 0) { src = wq; dst = g_Wq; }
    else if (which == 1) { src = wk; dst = g_Wk; }
    else if (which == 2) { src = wv; dst = g_Wv; }
    else                 { src = wo; dst = g_Wo; }
    float4 f = ((const float4*)src)[idx];
    bf162 lo, hi;
    lo.x = __float2bfloat16(f.x); lo.y = __float2bfloat16(f.y);
    hi.x = __float2bfloat16(f.z); hi.y = __float2bfloat16(f.w);
    bf162* d = (bf162*)(dst + idx * 4);
    d[0] = lo; d[1] = hi;
}

// ---------------- softmax over rows of 2048, in place ----------------
__global__ __launch_bounds__(256)
void softmax_kernel(bf16* __restrict__ P) {
    size_t row = blockIdx.x;
    bf162* p = (bf162*)(P + row * (size_t)NR);
    int t = threadIdx.x, lane = t & 31, w = t >> 5;
    __shared__ float red[8];

    float v[8];
    float mx = -1e30f;
    #pragma unroll
    for (int i = 0; i < 4; i++) {
        bf162 h = p[t + i * 256];
        v[2 * i]     = __bfloat162float(h.x);
        v[2 * i + 1] = __bfloat162float(h.y);
        mx = fmaxf(mx, fmaxf(v[2 * i], v[2 * i + 1]));
    }
    #pragma unroll
    for (int o = 16; o; o >>= 1) mx = fmaxf(mx, __shfl_xor_sync(0xffffffffu, mx, o));
    if (lane == 0) red[w] = mx;
    __syncthreads();
    mx = red[0];
    #pragma unroll
    for (int i = 1; i < 8; i++) mx = fmaxf(mx, red[i]);

    float s = 0.f;
    #pragma unroll
    for (int i = 0; i < 8; i++) { v[i] = __expf(v[i] - mx); s += v[i]; }
    #pragma unroll
    for (int o = 16; o; o >>= 1) s += __shfl_xor_sync(0xffffffffu, s, o);
    __syncthreads();
    if (lane == 0) red[w] = s;
    __syncthreads();
    s = red[0];
    #pragma unroll
    for (int i = 1; i < 8; i++) s += red[i];
    float inv = 1.0f / s;

    #pragma unroll
    for (int i = 0; i < 4; i++) {
        bf162 h;
        h.x = __float2bfloat16(v[2 * i] * inv);
        h.y = __float2bfloat16(v[2 * i + 1] * inv);
        p[t + i * 256] = h;
    }
}

// ---------------- residual + scatter into output sections ----------------
__global__ void scatter_kernel(const float* __restrict__ q,
                               const float* __restrict__ sa,
                               const float* __restrict__ si,
                               float* __restrict__ out) {
    size_t i = (size_t)blockIdx.x * blockDim.x + threadIdx.x;
    if (i >= (size_t)M1 * DIM / 2) return;
    int row = (int)(i >> 9);
    int d   = (int)((i & 511) * 2);
    int b = row / 25, t = row - b * 25;
    const float* src; size_t off, base;
    if (t == 0)       { src = q;  off = (size_t)b * 1024;                   base = 0; }
    else if (t <= 12) { src = sa; off = ((size_t)b * 12 + (t - 1)) * 1024;  base = (size_t)BATCH * 1024; }
    else              { src = si; off = ((size_t)b * 12 + (t - 13)) * 1024; base = (size_t)BATCH * 1024 * 13; }
    float2 sv = *(const float2*)(src + off + d);
    bf162  h  = *(const bf162*)(g_Sh + (size_t)row * DIM + d);
    float2 o;
    o.x = sv.x + __bfloat162float(h.x);
    o.y = sv.y + __bfloat162float(h.y);
    *(float2*)(out + base + off + d) = o;
}

// ---------------- launch ----------------
extern "C" void kernel_launch(void* const* d_in, const int* in_sizes, int n_in,
                              void* d_out, int out_size) {
    const float* q   = (const float*)d_in[0];
    const float* sa  = (const float*)d_in[1];
    const float* si  = (const float*)d_in[2];
    const float* ref = (const float*)d_in[5];
    const float* Wq  = (const float*)d_in[6];
    const float* bq  = (const float*)d_in[7];
    const float* Wk  = (const float*)d_in[8];
    const float* bk  = (const float*)d_in[9];
    const float* Wv  = (const float*)d_in[10];
    const float* bv  = (const float*)d_in[11];
    const float* Wo  = (const float*)d_in[12];
    const float* bo  = (const float*)d_in[13];
    float* out = (float*)d_out;

    static bf16 *pSf = nullptr, *pRef, *pWq, *pWk, *pWv, *pWo,
                *pQ, *pK, *pV, *pP, *pO, *pSh;
    if (!pSf) {
        cudaGetSymbolAddress((void**)&pSf,  g_Sf);
        cudaGetSymbolAddress((void**)&pRef, g_ref);
        cudaGetSymbolAddress((void**)&pWq,  g_Wq);
        cudaGetSymbolAddress((void**)&pWk,  g_Wk);
        cudaGetSymbolAddress((void**)&pWv,  g_Wv);
        cudaGetSymbolAddress((void**)&pWo,  g_Wo);
        cudaGetSymbolAddress((void**)&pQ,   g_Q);
        cudaGetSymbolAddress((void**)&pK,   g_K);
        cudaGetSymbolAddress((void**)&pV,   g_V);
        cudaGetSymbolAddress((void**)&pP,   g_P);
        cudaGetSymbolAddress((void**)&pO,   g_O);
        cudaGetSymbolAddress((void**)&pSh,  g_Sh);
        cudaFuncSetAttribute(gemm_kernel<false>, cudaFuncAttributeMaxDynamicSharedMemorySize, GEMM_SMEM);
        cudaFuncSetAttribute(gemm_kernel<true>,  cudaFuncAttributeMaxDynamicSharedMemorySize, GEMM_SMEM);
    }

    // launches 0-2: packing
    build_sf_kernel<<<(M1 * DIM / 4) / 256, 256>>>(q, sa, si);
    cvt_kernel<<<((size_t)NR * DIM / 4) / 256, 256>>>(pRef, ref);
    cvt_weights_kernel<<<(4 * WELEMS / 4) / 256, 256>>>(Wq, Wk, Wv, Wo);

    // launches 3-5: projections (launch 5 = V projection gets profiled)
    gemm_kernel<false><<<dim3(HA / 128, M1 / 128, 1), 256, GEMM_SMEM>>>(
        pSf, DIM, 0, pWq, HA, 0, pQ, HA, 0, DIM, bq, 1.0f);
    gemm_kernel<false><<<dim3(HA / 128, NR / 128, 1), 256, GEMM_SMEM>>>(
        pRef, DIM, 0, pWk, HA, 0, pK, HA, 0, DIM, bk, 1.0f);
    gemm_kernel<false><<<dim3(HA / 128, NR / 128, 1), 256, GEMM_SMEM>>>(
        pRef, DIM, 0, pWv, HA, 0, pV, HA, 0, DIM, bv, 1.0f);

    // scores[h] = BETA * Q_h @ K_h^T   (B = K [NR, HA] read in NT mode, no transpose)
    gemm_kernel<true><<<dim3(NR / 128, M1 / 128, NH), 256, GEMM_SMEM>>>(
        pQ, HA, HD,
        pK, HA, HD,
        pP, NR, (long long)M1 * NR,
        HD, nullptr, BETA_F);

    // softmax rows
    softmax_kernel<<<NH * M1, 256>>>(pP);

    // out[h] = P_h @ V_h   (NN mode)
    gemm_kernel<false><<<dim3(HD / 128, M1 / 128, NH), 256, GEMM_SMEM>>>(
        pP, NR, (long long)M1 * NR,
        pV, HA, HD,
        pO, HA, HD,
        NR, nullptr, 1.0f);

    // Sh = O @ Wo + bo
    gemm_kernel<false><<<dim3(DIM / 128, M1 / 128, 1), 256, GEMM_SMEM>>>(
        pO, HA, 0, pWo, DIM, 0, pSh, DIM, 0, HA, bo, 1.0f);

    // residual + scatter into (query, actives, inactives) sections
    scatter_kernel<<<(M1 * DIM / 2 + 255) / 256, 256>>>(q, sa, si, out);
}